// round 2
// baseline (speedup 1.0000x reference)
#include <cuda_runtime.h>
#include <math.h>

#define BB 4
#define NN 96
#define CC 64

// ---------------- device scratch (static: no runtime allocation allowed) ----------------
__device__ float g_P[(size_t)BB * NN * CC * 16 * 16 * 2];   // 50.3 MB pair products
__device__ float g_cat[16121856];                           // 64.5 MB cat buffers (all l)
__device__ float g_CG[4 * 4 * 4 * 7 * 7 * 7];               // dense CG table

// ---------------- constant tables ----------------
__constant__ int PBASE[4]    = {0, 1, 4, 9};
__constant__ int L1_OF_P[16] = {0, 1,1,1, 2,2,2,2,2, 3,3,3,3,3,3,3};
__constant__ int PAIR_OFF[5] = {0, 4, 13, 24, 34};
__constant__ int PAIR_L1[34] = {
    0,1,2,3,                    // l=0
    0,1,1,1,2,2,2,3,3,          // l=1
    0,1,1,1,2,2,2,2,3,3,3,      // l=2
    0,1,1,2,2,2,3,3,3,3};       // l=3
__constant__ int PAIR_L2[34] = {
    0,1,2,3,
    1,0,1,2,1,2,3,2,3,
    2,1,2,3,0,1,2,3,1,2,3,
    3,2,3,1,2,3,0,1,2,3};
__constant__ int NPAIR[4] = {4, 9, 11, 10};
__constant__ int TW[4]    = {576, 1216, 1472, 1344};
__constant__ size_t CAT_OFF[4] = {0, 442368, 3244032, 8896512};
__constant__ size_t OUT_OFF[4] = {0, 49152, 196608, 442368};
__constant__ int SLOT_CUM[4] = {0, 9, 66, 181};   // slot start per l (total 328)

// ---------------- init: Clebsch-Gordan table (deterministic, runs every launch) ----------------
__device__ double dfact(int n) { double r = 1.0; for (int i = 2; i <= n; i++) r *= (double)i; return r; }

__global__ void init_cg() {
    int idx = blockIdx.x * blockDim.x + threadIdx.x;
    const int total = 4 * 4 * 4 * 7 * 7 * 7;
    for (int t = idx; t < total; t += gridDim.x * blockDim.x) {
        int m  = t % 7; int r = t / 7;
        int j2 = r % 7; r /= 7;
        int i1 = r % 7; r /= 7;
        int l  = r % 4; r /= 4;
        int l2 = r % 4; r /= 4;
        int l1 = r;
        float v = 0.f;
        if (i1 <= 2 * l1 && j2 <= 2 * l2 && m <= 2 * l &&
            l >= abs(l1 - l2) && l <= l1 + l2) {
            int m1 = i1 - l1, m2 = j2 - l2, mm = m - l;
            if (mm == m1 + m2) {
                double pre = sqrt((2.0 * l + 1.0) * dfact(l + l1 - l2) * dfact(l - l1 + l2) *
                                  dfact(l1 + l2 - l) / dfact(l1 + l2 + l + 1));
                pre *= sqrt(dfact(l + mm) * dfact(l - mm) * dfact(l1 - m1) * dfact(l1 + m1) *
                            dfact(l2 - m2) * dfact(l2 + m2));
                int kmin = max(0, max(l2 - l - m1, l1 - l + m2));
                int kmax = min(l1 + l2 - l, min(l1 - m1, l2 + m2));
                double s = 0.0;
                for (int k = kmin; k <= kmax; k++) {
                    double term = 1.0 / (dfact(k) * dfact(l1 + l2 - l - k) * dfact(l1 - m1 - k) *
                                         dfact(l2 + m2 - k) * dfact(l - l2 + m1 + k) * dfact(l - l1 - m2 + k));
                    s += (k & 1) ? -term : term;
                }
                v = (float)(pre * s);
            }
        }
        g_CG[t] = v;
    }
}

// ---------------- k1: P[b,i,c,p,q] = sum_j E[b,i,j,c,p] * A[b,j,c,q] (complex) ----------------
// grid (8 c-chunks, N, B); 256 threads; warp = c within chunk; lane: p = lane>>1, q-half = lane&1
__global__ void __launch_bounds__(256) k1_pair(
    const float* __restrict__ e0, const float* __restrict__ e1,
    const float* __restrict__ e2, const float* __restrict__ e3,
    const float* __restrict__ a0, const float* __restrict__ a1,
    const float* __restrict__ a2, const float* __restrict__ a3)
{
    const int cchunk = blockIdx.x;
    const int i = blockIdx.y, b = blockIdx.z;
    const int c0 = cchunk * 8;
    const int tid = threadIdx.x;
    const int warp = tid >> 5, lane = tid & 31;
    const int p = lane >> 1, qh = lane & 1;
    const int cw = warp;

    __shared__ float Es[4][8][16][2];
    __shared__ float As[4][8][16][2];

    // loader role: threads 0..127 load E tile, 128..255 load A tile
    const bool isE = tid < 128;
    const int li = isE ? tid : tid - 128;
    const int lc = li >> 4;     // c_loc 0..7
    const int lp = li & 15;     // global p/q index 0..15
    const int ll = L1_OF_P[lp];
    const int lm = lp - PBASE[ll];
    const float* src;
    size_t base, stride;
    if (isE) {
        src = (ll == 0) ? e0 : (ll == 1) ? e1 : (ll == 2) ? e2 : e3;
        base   = ((((size_t)(b * NN + i) * NN + 0) * CC + (c0 + lc)) * (2 * ll + 1) + lm) * 2;
        stride = (size_t)CC * (2 * ll + 1) * 2;
    } else {
        src = (ll == 0) ? a0 : (ll == 1) ? a1 : (ll == 2) ? a2 : a3;
        base   = (((size_t)(b * NN + 0) * CC + (c0 + lc)) * (2 * ll + 1) + lm) * 2;
        stride = (size_t)CC * (2 * ll + 1) * 2;
    }

    float accr[8], acci[8];
#pragma unroll
    for (int q = 0; q < 8; q++) { accr[q] = 0.f; acci[q] = 0.f; }

    for (int j0 = 0; j0 < NN; j0 += 4) {
#pragma unroll
        for (int jj = 0; jj < 4; jj++) {
            float2 v = *(const float2*)(src + base + (size_t)(j0 + jj) * stride);
            if (isE) { Es[jj][lc][lp][0] = v.x; Es[jj][lc][lp][1] = v.y; }
            else     { As[jj][lc][lp][0] = v.x; As[jj][lc][lp][1] = v.y; }
        }
        __syncthreads();
#pragma unroll
        for (int jj = 0; jj < 4; jj++) {
            const float er = Es[jj][cw][p][0], ei = Es[jj][cw][p][1];
            const float4* ap4 = (const float4*)&As[jj][cw][qh * 8][0];
            float4 A01 = ap4[0], A23 = ap4[1], A45 = ap4[2], A67 = ap4[3];
            const float ar[8] = {A01.x, A01.z, A23.x, A23.z, A45.x, A45.z, A67.x, A67.z};
            const float ai[8] = {A01.y, A01.w, A23.y, A23.w, A45.y, A45.w, A67.y, A67.w};
#pragma unroll
            for (int q = 0; q < 8; q++) {
                accr[q] = fmaf(er, ar[q], accr[q]);
                accr[q] = fmaf(-ei, ai[q], accr[q]);
                acci[q] = fmaf(er, ai[q], acci[q]);
                acci[q] = fmaf(ei, ar[q], acci[q]);
            }
        }
        __syncthreads();
    }
    size_t pbase = (((size_t)(b * NN + i) * CC + c0 + cw) * 256 + p * 16 + qh * 8) * 2;
#pragma unroll
    for (int q = 0; q < 8; q++) {
        g_P[pbase + q * 2]     = accr[q];
        g_P[pbase + q * 2 + 1] = acci[q];
    }
}

// ---------------- k2: CG contraction of P, identity, self tensor-product -> cat buffers ----------------
// grid (4 c-chunks of 16, N, B); 256 threads
__global__ void __launch_bounds__(256) k2_cg(
    const float* __restrict__ a0, const float* __restrict__ a1,
    const float* __restrict__ a2, const float* __restrict__ a3)
{
    const int cchunk = blockIdx.x;
    const int i = blockIdx.y, b = blockIdx.z;
    const int c0 = cchunk * 16;
    const int bi = b * NN + i;
    const int tid = threadIdx.x;

    __shared__ float Ps[16 * 516];    // P per c, padded stride
    __shared__ float Asm[16 * 34];    // atoms per c: 16 complex + pad

    const float4* psrc = (const float4*)(g_P + ((size_t)bi * CC + c0) * 512);
    for (int t = tid; t < 16 * 128; t += 256) {
        int cl = t >> 7, x4 = t & 127;
        float4 v = psrc[cl * 128 + x4];
        *(float4*)&Ps[cl * 516 + x4 * 4] = v;
    }
    for (int t = tid; t < 16 * 32; t += 256) {
        int cl = t >> 5, x = t & 31;
        int pg = x >> 1, ri = x & 1;
        int l2 = L1_OF_P[pg], mm = pg - PBASE[l2];
        const float* ap = (l2 == 0) ? a0 : (l2 == 1) ? a1 : (l2 == 2) ? a2 : a3;
        Asm[cl * 34 + x] = ap[(((size_t)bi * CC + c0 + cl) * (2 * l2 + 1) + mm) * 2 + ri];
    }
    __syncthreads();

    for (int it = tid; it < 328 * 16; it += 256) {
        int slot = it >> 4, cl = it & 15;
        int l = (slot < 9) ? 0 : (slot < 66) ? 1 : (slot < 181) ? 2 : 3;
        int sp = slot - SLOT_CUM[l];
        int dim = 2 * l + 1;
        int blk = sp / dim, m = sp % dim;
        int np = NPAIR[l];
        float zr = 0.f, zi = 0.f;
        if (blk == np) {                              // identity section
            int pg = PBASE[l] + m;
            zr = Asm[cl * 34 + pg * 2];
            zi = Asm[cl * 34 + pg * 2 + 1];
        } else {
            int k = (blk < np) ? blk : blk - np - 1;
            int l1 = PAIR_L1[PAIR_OFF[l] + k], l2 = PAIR_L2[PAIR_OFF[l] + k];
            const float* cg = &g_CG[((l1 * 4 + l2) * 4 + l) * 343];
            if (blk < np) {                           // aggregate section (reads P)
                const float* pc = &Ps[cl * 516];
                for (int i1 = 0; i1 <= 2 * l1; i1++) {
                    int j2 = m - l - i1 + l1 + l2;
                    if (j2 >= 0 && j2 <= 2 * l2) {
                        float coef = cg[(i1 * 7 + j2) * 7 + m];
                        int pp = PBASE[l1] + i1, qq = PBASE[l2] + j2;
                        zr = fmaf(coef, pc[(pp * 16 + qq) * 2], zr);
                        zi = fmaf(coef, pc[(pp * 16 + qq) * 2 + 1], zi);
                    }
                }
            } else {                                  // square section (atoms x atoms)
                const float* am = &Asm[cl * 34];
                for (int i1 = 0; i1 <= 2 * l1; i1++) {
                    int j2 = m - l - i1 + l1 + l2;
                    if (j2 >= 0 && j2 <= 2 * l2) {
                        float coef = cg[(i1 * 7 + j2) * 7 + m];
                        int pp = PBASE[l1] + i1, qq = PBASE[l2] + j2;
                        float x1r = am[pp * 2], x1i = am[pp * 2 + 1];
                        float x2r = am[qq * 2], x2i = am[qq * 2 + 1];
                        zr = fmaf(coef, x1r * x2r - x1i * x2i, zr);
                        zi = fmaf(coef, x1r * x2i + x1i * x2r, zi);
                    }
                }
            }
        }
        size_t addr = CAT_OFF[l] + ((size_t)(bi * dim + m) * TW[l] + blk * CC + c0 + cl) * 2;
        g_cat[addr]     = zr;
        g_cat[addr + 1] = zi;
    }
}

// ---------------- k3: fused complex GEMM out[row,d] = sum_T cat[row,T] * w[d,T] ----------------
// rows = (b,i,m); 32-row x 64-d tiles; 192 blocks total across all l
__global__ void __launch_bounds__(256) k3_gemm(
    const float* __restrict__ w0, const float* __restrict__ w1,
    const float* __restrict__ w2, const float* __restrict__ w3,
    float* __restrict__ out)
{
    const int blk = blockIdx.x;
    int l, rt0;
    if      (blk < 12)  { l = 0; rt0 = blk; }
    else if (blk < 48)  { l = 1; rt0 = blk - 12; }
    else if (blk < 108) { l = 2; rt0 = blk - 48; }
    else                { l = 3; rt0 = blk - 108; }
    const int T = TW[l], dim = 2 * l + 1;
    const int row0 = rt0 * 32;
    const float* wsrc = (l == 0) ? w0 : (l == 1) ? w1 : (l == 2) ? w2 : w3;
    const float* catl = g_cat + CAT_OFF[l];

    __shared__ float cs[32 * 72];    // [k][row*2 + ri], padded stride 72
    __shared__ float ws[32 * 132];   // [k][d*2 + ri],  padded stride 132

    const int tid = threadIdx.x;
    const int rq = tid >> 5, L = tid & 31;
    float acc[4][2][2];
#pragma unroll
    for (int r = 0; r < 4; r++)
#pragma unroll
        for (int d = 0; d < 2; d++) { acc[r][d][0] = 0.f; acc[r][d][1] = 0.f; }

    const int nK = T >> 5;
    for (int kt = 0; kt < nK; kt++) {
        const int T0 = kt * 32;
#pragma unroll
        for (int t = tid; t < 1024; t += 256) {
            int r = t >> 5, k = t & 31;
            float2 v = *(const float2*)(catl + ((size_t)(row0 + r) * T + T0 + k) * 2);
            cs[k * 72 + r * 2]     = v.x;
            cs[k * 72 + r * 2 + 1] = v.y;
        }
#pragma unroll
        for (int t = tid; t < 2048; t += 256) {
            int d = t >> 5, k = t & 31;
            float2 v = *(const float2*)(wsrc + ((size_t)d * T + T0 + k) * 2);
            ws[k * 132 + d * 2]     = v.x;
            ws[k * 132 + d * 2 + 1] = v.y;
        }
        __syncthreads();
#pragma unroll 4
        for (int k = 0; k < 32; k++) {
            float4 c01 = *(const float4*)&cs[k * 72 + rq * 8];
            float4 c23 = *(const float4*)&cs[k * 72 + rq * 8 + 4];
            float4 wv  = *(const float4*)&ws[k * 132 + L * 4];
            const float cr[4] = {c01.x, c01.z, c23.x, c23.z};
            const float ci[4] = {c01.y, c01.w, c23.y, c23.w};
            const float wr[2] = {wv.x, wv.z};
            const float wi[2] = {wv.y, wv.w};
#pragma unroll
            for (int r = 0; r < 4; r++)
#pragma unroll
                for (int d = 0; d < 2; d++) {
                    acc[r][d][0] = fmaf(wr[d], cr[r], acc[r][d][0]);
                    acc[r][d][0] = fmaf(-wi[d], ci[r], acc[r][d][0]);
                    acc[r][d][1] = fmaf(wr[d], ci[r], acc[r][d][1]);
                    acc[r][d][1] = fmaf(wi[d], cr[r], acc[r][d][1]);
                }
        }
        __syncthreads();
    }

    float* ob = out + OUT_OFF[l];
#pragma unroll
    for (int r = 0; r < 4; r++) {
        int grow = row0 + rq * 4 + r;
        int bi = grow / dim, m = grow % dim;
#pragma unroll
        for (int d = 0; d < 2; d++) {
            size_t addr = ((size_t)(bi * CC + L * 2 + d) * dim + m) * 2;
            ob[addr]     = acc[r][d][0];
            ob[addr + 1] = acc[r][d][1];
        }
    }
}

// ---------------- launch ----------------
extern "C" void kernel_launch(void* const* d_in, const int* in_sizes, int n_in,
                              void* d_out, int out_size)
{
    const float *atomp[4] = {0, 0, 0, 0}, *edgep[4] = {0, 0, 0, 0}, *wp[4] = {0, 0, 0, 0};
    for (int idx = 0; idx < n_in; idx++) {
        int s = in_sizes[idx];
        const float* ptr = (const float*)d_in[idx];
        switch (s) {
            case 49152:    atomp[0] = ptr; break;
            case 147456:   atomp[1] = ptr; break;
            case 245760:   atomp[2] = ptr; break;
            case 344064:   atomp[3] = ptr; break;
            case 4718592:  edgep[0] = ptr; break;
            case 14155776: edgep[1] = ptr; break;
            case 23592960: edgep[2] = ptr; break;
            case 33030144: edgep[3] = ptr; break;
            case 73728:    wp[0] = ptr; break;
            case 155648:   wp[1] = ptr; break;
            case 188416:   wp[2] = ptr; break;
            case 172032:   wp[3] = ptr; break;
            default: break; // mask (384) unused
        }
    }
    init_cg<<<32, 256>>>();
    dim3 g1(8, NN, BB);
    k1_pair<<<g1, 256>>>(edgep[0], edgep[1], edgep[2], edgep[3],
                         atomp[0], atomp[1], atomp[2], atomp[3]);
    dim3 g2(4, NN, BB);
    k2_cg<<<g2, 256>>>(atomp[0], atomp[1], atomp[2], atomp[3]);
    k3_gemm<<<192, 256>>>(wp[0], wp[1], wp[2], wp[3], (float*)d_out);
}

// round 6
// speedup vs baseline: 1.1238x; 1.1238x over previous
#include <cuda_runtime.h>
#include <math.h>

#define BB 4
#define NN 96
#define CC 64

// ---------------- device scratch (static: no runtime allocation allowed) ----------------
__device__ float g_P[(size_t)BB * NN * CC * 16 * 16 * 2];   // 50.3 MB pair products
__device__ float g_cat[16121856];                           // 64.5 MB cat buffers (all l)
__device__ float g_CG[4 * 4 * 4 * 7 * 7 * 7];               // dense CG table

// ---------------- constant tables ----------------
__constant__ int PBASE[4]    = {0, 1, 4, 9};
__constant__ int L1_OF_P[16] = {0, 1,1,1, 2,2,2,2,2, 3,3,3,3,3,3,3};
__constant__ int PAIR_OFF[5] = {0, 4, 13, 24, 34};
__constant__ int PAIR_L1[34] = {
    0,1,2,3,
    0,1,1,1,2,2,2,3,3,
    0,1,1,1,2,2,2,2,3,3,3,
    0,1,1,2,2,2,3,3,3,3};
__constant__ int PAIR_L2[34] = {
    0,1,2,3,
    1,0,1,2,1,2,3,2,3,
    2,1,2,3,0,1,2,3,1,2,3,
    3,2,3,1,2,3,0,1,2,3};
__constant__ int NPAIR[4] = {4, 9, 11, 10};
__constant__ int TW[4]    = {576, 1216, 1472, 1344};
__constant__ size_t CAT_OFF[4] = {0, 442368, 3244032, 8896512};
__constant__ size_t OUT_OFF[4] = {0, 49152, 196608, 442368};
__constant__ int SLOT_CUM[4] = {0, 9, 66, 181};

// ---------------- init: Clebsch-Gordan table ----------------
__device__ double dfact(int n) { double r = 1.0; for (int i = 2; i <= n; i++) r *= (double)i; return r; }

__global__ void init_cg() {
    int idx = blockIdx.x * blockDim.x + threadIdx.x;
    const int total = 4 * 4 * 4 * 7 * 7 * 7;
    for (int t = idx; t < total; t += gridDim.x * blockDim.x) {
        int m  = t % 7; int r = t / 7;
        int j2 = r % 7; r /= 7;
        int i1 = r % 7; r /= 7;
        int l  = r % 4; r /= 4;
        int l2 = r % 4; r /= 4;
        int l1 = r;
        float v = 0.f;
        if (i1 <= 2 * l1 && j2 <= 2 * l2 && m <= 2 * l &&
            l >= abs(l1 - l2) && l <= l1 + l2) {
            int m1 = i1 - l1, m2 = j2 - l2, mm = m - l;
            if (mm == m1 + m2) {
                double pre = sqrt((2.0 * l + 1.0) * dfact(l + l1 - l2) * dfact(l - l1 + l2) *
                                  dfact(l1 + l2 - l) / dfact(l1 + l2 + l + 1));
                pre *= sqrt(dfact(l + mm) * dfact(l - mm) * dfact(l1 - m1) * dfact(l1 + m1) *
                            dfact(l2 - m2) * dfact(l2 + m2));
                int kmin = max(0, max(l2 - l - m1, l1 - l + m2));
                int kmax = min(l1 + l2 - l, min(l1 - m1, l2 + m2));
                double s = 0.0;
                for (int k = kmin; k <= kmax; k++) {
                    double term = 1.0 / (dfact(k) * dfact(l1 + l2 - l - k) * dfact(l1 - m1 - k) *
                                         dfact(l2 + m2 - k) * dfact(l - l2 + m1 + k) * dfact(l - l1 - m2 + k));
                    s += (k & 1) ? -term : term;
                }
                v = (float)(pre * s);
            }
        }
        g_CG[t] = v;
    }
}

// ---------------- k1: P[b,i,c,p,q] = sum_j E[b,i,j,c,p] * A[b,j,c,q] (complex, scalar FFMA) ----------------
// grid (4 c-chunks of 16, N, B) = 1536 CTAs, 256 threads
// Each thread owns one (c_loc, p) and accumulates all 16 q values.
#define JT 8
__global__ void __launch_bounds__(256) k1_pair(
    const float* __restrict__ e0, const float* __restrict__ e1,
    const float* __restrict__ e2, const float* __restrict__ e3,
    const float* __restrict__ a0, const float* __restrict__ a1,
    const float* __restrict__ a2, const float* __restrict__ a3)
{
    const int cchunk = blockIdx.x;
    const int i = blockIdx.y, bb = blockIdx.z;
    const int c0 = cchunk * 16;
    const int bi = bb * NN + i;
    const int tid = threadIdx.x;

    __shared__ __align__(16) float Es[JT * 16 * 32];   // [jj][c][p][{re,im}]
    __shared__ __align__(16) float As[JT * 16 * 32];   // [jj][c][q][{re,im}]

    // loader mapping: contiguous (c,m) per l so LDGs coalesce within each l-tensor
    int ll, tg;
    if (tid < 16)       { ll = 0; tg = tid; }
    else if (tid < 64)  { ll = 1; tg = tid - 16; }
    else if (tid < 144) { ll = 2; tg = tid - 64; }
    else                { ll = 3; tg = tid - 144; }
    const int dimL = 2 * ll + 1;
    const int lc = tg / dimL, lm = tg - lc * dimL;
    const int lp = PBASE[ll] + lm;
    const float* esrc = (ll == 0) ? e0 : (ll == 1) ? e1 : (ll == 2) ? e2 : e3;
    const float* asrc = (ll == 0) ? a0 : (ll == 1) ? a1 : (ll == 2) ? a2 : a3;
    const size_t estride = (size_t)CC * dimL * 2;
    const size_t ebase = ((size_t)bi * NN * CC + (c0 + lc)) * dimL * 2 + lm * 2;
    const size_t abase = ((size_t)bb * NN * CC + (c0 + lc)) * dimL * 2 + lm * 2;

    // compute mapping: warp covers 2 c's x 16 p's
    const int w = tid >> 5, lane = tid & 31;
    const int ch = lane >> 4, p = lane & 15;
    const int cloc = w * 2 + ch;

    float accR[16], accI[16];
#pragma unroll
    for (int q = 0; q < 16; q++) { accR[q] = 0.f; accI[q] = 0.f; }

    for (int j0 = 0; j0 < NN; j0 += JT) {
#pragma unroll
        for (int jj = 0; jj < JT; jj++) {
            float2 ev = *(const float2*)(esrc + ebase + (size_t)(j0 + jj) * estride);
            float2 av = *(const float2*)(asrc + abase + (size_t)(j0 + jj) * estride);
            *(float2*)&Es[(jj * 16 + lc) * 32 + lp * 2] = ev;
            *(float2*)&As[(jj * 16 + lc) * 32 + lp * 2] = av;
        }
        __syncthreads();
#pragma unroll
        for (int jj = 0; jj < JT; jj++) {
            float2 e = *(const float2*)&Es[(jj * 16 + cloc) * 32 + p * 2];
            const float4* ap = (const float4*)&As[(jj * 16 + cloc) * 32];
#pragma unroll
            for (int t = 0; t < 8; t++) {
                float4 v = ap[t];          // q = 2t (v.x,v.y), q = 2t+1 (v.z,v.w)
                accR[2 * t]     = fmaf(e.x, v.x, accR[2 * t]);
                accR[2 * t]     = fmaf(-e.y, v.y, accR[2 * t]);
                accI[2 * t]     = fmaf(e.x, v.y, accI[2 * t]);
                accI[2 * t]     = fmaf(e.y, v.x, accI[2 * t]);
                accR[2 * t + 1] = fmaf(e.x, v.z, accR[2 * t + 1]);
                accR[2 * t + 1] = fmaf(-e.y, v.w, accR[2 * t + 1]);
                accI[2 * t + 1] = fmaf(e.x, v.w, accI[2 * t + 1]);
                accI[2 * t + 1] = fmaf(e.y, v.z, accI[2 * t + 1]);
            }
        }
        __syncthreads();
    }
    // write P[bi, c0+cloc, p, q, {re,im}] — 32 contiguous floats per thread
    float4* pout = (float4*)(g_P + (((size_t)bi * CC + c0 + cloc) * 256 + p * 16) * 2);
#pragma unroll
    for (int t = 0; t < 8; t++) {
        pout[t] = make_float4(accR[2 * t], accI[2 * t], accR[2 * t + 1], accI[2 * t + 1]);
    }
}

// ---------------- k2: CG contraction of P, identity, self tensor-product -> cat ----------------
__global__ void __launch_bounds__(256) k2_cg(
    const float* __restrict__ a0, const float* __restrict__ a1,
    const float* __restrict__ a2, const float* __restrict__ a3)
{
    const int cchunk = blockIdx.x;
    const int i = blockIdx.y, b = blockIdx.z;
    const int c0 = cchunk * 16;
    const int bi = b * NN + i;
    const int tid = threadIdx.x;

    __shared__ float Ps[16 * 516];
    __shared__ float Asm[16 * 34];

    const float4* psrc = (const float4*)(g_P + ((size_t)bi * CC + c0) * 512);
    for (int t = tid; t < 16 * 128; t += 256) {
        int cl = t >> 7, x4 = t & 127;
        float4 v = psrc[cl * 128 + x4];
        *(float4*)&Ps[cl * 516 + x4 * 4] = v;
    }
    for (int t = tid; t < 16 * 32; t += 256) {
        int cl = t >> 5, x = t & 31;
        int pg = x >> 1, ri = x & 1;
        int l2 = L1_OF_P[pg], mm = pg - PBASE[l2];
        const float* ap = (l2 == 0) ? a0 : (l2 == 1) ? a1 : (l2 == 2) ? a2 : a3;
        Asm[cl * 34 + x] = ap[(((size_t)bi * CC + c0 + cl) * (2 * l2 + 1) + mm) * 2 + ri];
    }
    __syncthreads();

    for (int it = tid; it < 328 * 16; it += 256) {
        int slot = it >> 4, cl = it & 15;
        int l = (slot < 9) ? 0 : (slot < 66) ? 1 : (slot < 181) ? 2 : 3;
        int sp = slot - SLOT_CUM[l];
        int dim = 2 * l + 1;
        int blk = sp / dim, m = sp % dim;
        int np = NPAIR[l];
        float zr = 0.f, zi = 0.f;
        if (blk == np) {
            int pg = PBASE[l] + m;
            zr = Asm[cl * 34 + pg * 2];
            zi = Asm[cl * 34 + pg * 2 + 1];
        } else {
            int k = (blk < np) ? blk : blk - np - 1;
            int l1 = PAIR_L1[PAIR_OFF[l] + k], l2 = PAIR_L2[PAIR_OFF[l] + k];
            const float* cg = &g_CG[((l1 * 4 + l2) * 4 + l) * 343];
            if (blk < np) {
                const float* pc = &Ps[cl * 516];
                for (int i1 = 0; i1 <= 2 * l1; i1++) {
                    int j2 = m - l - i1 + l1 + l2;
                    if (j2 >= 0 && j2 <= 2 * l2) {
                        float coef = cg[(i1 * 7 + j2) * 7 + m];
                        int pp = PBASE[l1] + i1, qq = PBASE[l2] + j2;
                        zr = fmaf(coef, pc[(pp * 16 + qq) * 2], zr);
                        zi = fmaf(coef, pc[(pp * 16 + qq) * 2 + 1], zi);
                    }
                }
            } else {
                const float* am = &Asm[cl * 34];
                for (int i1 = 0; i1 <= 2 * l1; i1++) {
                    int j2 = m - l - i1 + l1 + l2;
                    if (j2 >= 0 && j2 <= 2 * l2) {
                        float coef = cg[(i1 * 7 + j2) * 7 + m];
                        int pp = PBASE[l1] + i1, qq = PBASE[l2] + j2;
                        float x1r = am[pp * 2], x1i = am[pp * 2 + 1];
                        float x2r = am[qq * 2], x2i = am[qq * 2 + 1];
                        zr = fmaf(coef, x1r * x2r - x1i * x2i, zr);
                        zi = fmaf(coef, x1r * x2i + x1i * x2r, zi);
                    }
                }
            }
        }
        size_t addr = CAT_OFF[l] + ((size_t)(bi * dim + m) * TW[l] + blk * CC + c0 + cl) * 2;
        g_cat[addr]     = zr;
        g_cat[addr + 1] = zi;
    }
}

// ---------------- k3: fused complex GEMM (scalar FFMA), 16-row x 64-d tiles, 384 CTAs ----------------
// Each thread owns 2 rows x 2 d = 4 complex accumulators.
// cs stride is 36 floats (144 B) so the float4 compute reads are 16B-aligned for every k.
__global__ void __launch_bounds__(256) k3_gemm(
    const float* __restrict__ w0, const float* __restrict__ w1,
    const float* __restrict__ w2, const float* __restrict__ w3,
    float* __restrict__ out)
{
    const int blk = blockIdx.x;
    int l, rt0;
    if      (blk < 24)  { l = 0; rt0 = blk; }
    else if (blk < 96)  { l = 1; rt0 = blk - 24; }
    else if (blk < 216) { l = 2; rt0 = blk - 96; }
    else                { l = 3; rt0 = blk - 216; }
    const int T = TW[l], dim = 2 * l + 1;
    const int row0 = rt0 * 16;
    const float* wsrc = (l == 0) ? w0 : (l == 1) ? w1 : (l == 2) ? w2 : w3;
    const float* catl = g_cat + CAT_OFF[l];

    __shared__ __align__(16) float cs[32 * 36];    // [k][row][{re,im}], stride 36 floats (16B-aligned rows)
    __shared__ __align__(16) float ws[32 * 132];   // [k][d][{re,im}],  stride 132 floats (528 B, 16B-divisible)

    const int tid = threadIdx.x;
    const int rg = tid >> 5, L = tid & 31;     // rows rg*2, rg*2+1 ; d = 2L, 2L+1

    float accR[2][2], accI[2][2];
#pragma unroll
    for (int r = 0; r < 2; r++)
#pragma unroll
        for (int d = 0; d < 2; d++) { accR[r][d] = 0.f; accI[r][d] = 0.f; }

    const int nK = T >> 5;
    for (int kt = 0; kt < nK; kt++) {
        const int T0 = kt * 32;
#pragma unroll
        for (int t = 0; t < 2; t++) {
            int idx = tid + t * 256;
            int r = idx >> 5, k = idx & 31;
            float2 v = *(const float2*)(catl + ((size_t)(row0 + r) * T + T0 + k) * 2);
            *(float2*)&cs[k * 36 + r * 2] = v;
        }
#pragma unroll
        for (int t = 0; t < 8; t++) {
            int idx = tid + t * 256;
            int d = idx >> 5, k = idx & 31;
            float2 v = *(const float2*)(wsrc + ((size_t)d * T + T0 + k) * 2);
            *(float2*)&ws[k * 132 + d * 2] = v;
        }
        __syncthreads();
#pragma unroll 4
        for (int k = 0; k < 32; k++) {
            float4 wv = *(const float4*)&ws[k * 132 + 4 * L];   // d=2L (x,y), d=2L+1 (z,w)
            float4 cv = *(const float4*)&cs[k * 36 + rg * 4];   // row rg*2 (x,y), rg*2+1 (z,w) — warp-uniform broadcast
            const float cr[2] = {cv.x, cv.z};
            const float ci[2] = {cv.y, cv.w};
            const float wr[2] = {wv.x, wv.z};
            const float wi[2] = {wv.y, wv.w};
#pragma unroll
            for (int r = 0; r < 2; r++)
#pragma unroll
                for (int d = 0; d < 2; d++) {
                    accR[r][d] = fmaf(wr[d], cr[r], accR[r][d]);
                    accR[r][d] = fmaf(-wi[d], ci[r], accR[r][d]);
                    accI[r][d] = fmaf(wr[d], ci[r], accI[r][d]);
                    accI[r][d] = fmaf(wi[d], cr[r], accI[r][d]);
                }
        }
        __syncthreads();
    }

    float* ob = out + OUT_OFF[l];
#pragma unroll
    for (int r = 0; r < 2; r++) {
        int grow = row0 + rg * 2 + r;
        int bi = grow / dim, m = grow - bi * dim;
#pragma unroll
        for (int d = 0; d < 2; d++) {
            size_t addr = ((size_t)(bi * CC + 2 * L + d) * dim + m) * 2;
            *(float2*)&ob[addr] = make_float2(accR[r][d], accI[r][d]);
        }
    }
}

// ---------------- launch ----------------
extern "C" void kernel_launch(void* const* d_in, const int* in_sizes, int n_in,
                              void* d_out, int out_size)
{
    const float *atomp[4] = {0, 0, 0, 0}, *edgep[4] = {0, 0, 0, 0}, *wp[4] = {0, 0, 0, 0};
    for (int idx = 0; idx < n_in; idx++) {
        int s = in_sizes[idx];
        const float* ptr = (const float*)d_in[idx];
        switch (s) {
            case 49152:    atomp[0] = ptr; break;
            case 147456:   atomp[1] = ptr; break;
            case 245760:   atomp[2] = ptr; break;
            case 344064:   atomp[3] = ptr; break;
            case 4718592:  edgep[0] = ptr; break;
            case 14155776: edgep[1] = ptr; break;
            case 23592960: edgep[2] = ptr; break;
            case 33030144: edgep[3] = ptr; break;
            case 73728:    wp[0] = ptr; break;
            case 155648:   wp[1] = ptr; break;
            case 188416:   wp[2] = ptr; break;
            case 172032:   wp[3] = ptr; break;
            default: break; // mask (384) unused
        }
    }
    init_cg<<<32, 256>>>();
    dim3 g1(4, NN, BB);
    k1_pair<<<g1, 256>>>(edgep[0], edgep[1], edgep[2], edgep[3],
                         atomp[0], atomp[1], atomp[2], atomp[3]);
    dim3 g2(4, NN, BB);
    k2_cg<<<g2, 256>>>(atomp[0], atomp[1], atomp[2], atomp[3]);
    k3_gemm<<<384, 256>>>(wp[0], wp[1], wp[2], wp[3], (float*)d_out);
}